// round 15
// baseline (speedup 1.0000x reference)
#include <cuda_runtime.h>
#include <cuda_fp16.h>
#include <math.h>

#define FH 50
#define FW 50
#define FC 1024
#define POOL 7
#define CELLS (FH * FW)
#define MAPW (CELLS * FC / 8)   // uint4 elements per map

// One contiguous pyramid: [0]=F (rn fp16), [1]=R (vert pair max), [2]=M2 (2x2 max).
// rn is monotone and max returns an input, so max(rn(a),rn(b)) == rn(max(a,b)):
// the fp16 pyramid equals rn() of the fp32 pyramid exactly.
__device__ __half g_pyr[3 * CELLS * FC];

__device__ __forceinline__ float4 max4(float4 a, float4 b) {
    return make_float4(fmaxf(a.x, b.x), fmaxf(a.y, b.y),
                       fmaxf(a.z, b.z), fmaxf(a.w, b.w));
}

// Build v2: 512 threads = 4 consecutive cells x 128 lanes. Each thread loads
// only its own vertical pair (2 cells), computes R; the horizontal neighbor's
// R comes from smem (or is computed directly at group/row boundaries).
// M2 = hmax(R(x), R(x+1)) in fp16 — exact by monotonicity of rn.
__global__ void __launch_bounds__(512) build_kernel(const float* __restrict__ fm) {
    __shared__ uint4 sR[4][128];     // fp16 R per cell-group per lane (8 KB)

    const int g    = threadIdx.x >> 7;
    const int lane = threadIdx.x & 127;
    const int c    = blockIdx.x * 4 + g;      // linear cell 0..2499
    const int y = c / FW;
    const int x = c - y * FW;
    const int yp = min(y + 1, FH - 1);
    const int xp = min(x + 1, FW - 1);

    const float4* f = reinterpret_cast<const float4*>(fm);
    const int l2 = lane * 2;

    float4 a00 = f[c * 256 + l2],              b00 = f[c * 256 + l2 + 1];
    float4 a10 = f[(yp * FW + x) * 256 + l2],  b10 = f[(yp * FW + x) * 256 + l2 + 1];

    float4 ra = max4(a00, a10);
    float4 rb = max4(b00, b10);

    union { __half2 h[4]; uint4 u; } pf, pr;
    pf.h[0] = __floats2half2_rn(a00.x, a00.y); pf.h[1] = __floats2half2_rn(a00.z, a00.w);
    pf.h[2] = __floats2half2_rn(b00.x, b00.y); pf.h[3] = __floats2half2_rn(b00.z, b00.w);
    pr.h[0] = __floats2half2_rn(ra.x, ra.y);   pr.h[1] = __floats2half2_rn(ra.z, ra.w);
    pr.h[2] = __floats2half2_rn(rb.x, rb.y);   pr.h[3] = __floats2half2_rn(rb.z, rb.w);

    uint4* pyr = reinterpret_cast<uint4*>(g_pyr);
    const int i = c * 128 + lane;
    pyr[i]        = pf.u;
    pyr[MAPW + i] = pr.u;
    sR[g][lane]   = pr.u;
    __syncthreads();

    // Neighbor cell's R (same lane).
    union { __half2 h[4]; uint4 u; } nr;
    if (xp == x) {
        nr.u = pr.u;                 // right edge: neighbor = self
    } else if (g < 3) {
        nr.u = sR[g + 1][lane];      // in-block neighbor (c+1 == y*FW+xp)
    } else {
        const int cn = y * FW + xp;  // block-boundary: compute directly
        float4 a01 = f[cn * 256 + l2],             b01 = f[cn * 256 + l2 + 1];
        float4 a11 = f[(yp * FW + xp) * 256 + l2], b11 = f[(yp * FW + xp) * 256 + l2 + 1];
        float4 qa = max4(a01, a11);
        float4 qb = max4(b01, b11);
        nr.h[0] = __floats2half2_rn(qa.x, qa.y); nr.h[1] = __floats2half2_rn(qa.z, qa.w);
        nr.h[2] = __floats2half2_rn(qb.x, qb.y); nr.h[3] = __floats2half2_rn(qb.z, qb.w);
    }

    union { __half2 h[4]; uint4 u; } pm;
    pm.h[0] = __hmax2(pr.h[0], nr.h[0]);
    pm.h[1] = __hmax2(pr.h[1], nr.h[1]);
    pm.h[2] = __hmax2(pr.h[2], nr.h[2]);
    pm.h[3] = __hmax2(pr.h[3], nr.h[3]);
    pyr[2 * MAPW + i] = pm.u;
}

// 512-thread blocks, FOUR bins per block: thread group (tid>>7) owns one bin,
// its 128 threads own one uint4 lane (8 halves) each. Per-thread logic is the
// R10/R14-proven pool (inline geometry, pyramid sampling).
__global__ void __launch_bounds__(512) roipool_kernel(
    const float* __restrict__ rois,  // [N,4] (y1,x1,y2,x2) normalized
    float* __restrict__ out)         // [N,7,7,1024] fp32
{
    const int bin = blockIdx.x * 4 + (threadIdx.x >> 7);   // 0..51
    if (bin >= 49) return;           // tail groups idle
    const int roi = blockIdx.y;
    const int by = bin / POOL;
    const int bx = bin - by * POOL;

    const float4 r = reinterpret_cast<const float4*>(rois)[roi];
    const int h0 = (int)(FH * r.x);
    const int w0 = (int)(FW * r.y);
    const int h1 = (int)(FH * r.z);
    const int w1 = (int)(FW * r.w);
    const int rh = h1 - h0;
    const int rw = w1 - w0;
    const int hstep = rh / POOL;
    const int wstep = rw / POOL;

    int sh = by * hstep;
    int eh = (by < POOL - 1) ? sh + hstep : rh;
    if (sh == eh) { if (eh < rh) eh += 1; else sh -= 1; }
    int sw = bx * wstep;
    int ew = (bx < POOL - 1) ? sw + wstep : rw;
    if (sw == ew) { if (ew < rw) ew += 1; else sw -= 1; }

    const int ys = max(h0 + sh, 0);
    const int ye = h0 + eh;          // <= FH
    const int xs = max(w0 + sw, 0);
    const int xe = w0 + ew;          // <= FW
    const int h = ye - ys;
    const int w = xe - xs;

    // Select map + sampling grid (overlapping clamped samples; max idempotent).
    const uint4* base;
    int yn, xn, xstep, ylast, xlast;
    if (h >= 2) {
        yn = (h + 1) >> 1; ylast = ye - 2;
        if (w >= 2) { base = reinterpret_cast<const uint4*>(g_pyr) + 2 * MAPW;
                      xn = (w + 1) >> 1; xstep = 2; xlast = xe - 2; }
        else        { base = reinterpret_cast<const uint4*>(g_pyr) + MAPW;
                      xn = 1; xstep = 2; xlast = xs; }
    } else {        // h == 1: single row from F
        base = reinterpret_cast<const uint4*>(g_pyr);
        yn = 1; ylast = ys; xn = w; xstep = 1; xlast = xe - 1;
    }

    const int t = threadIdx.x & 127; // uint4 lane (8 halves)
    const __half2 ninf = __float2half2_rn(-INFINITY);
    __half2 a0 = ninf, a1 = ninf, a2 = ninf, a3 = ninf;

    for (int iy = 0; iy < yn; ++iy) {
        const int y = min(ys + 2 * iy, ylast);
        const uint4* row = base + (size_t)(y * FW) * (FC / 8) + t;
        #pragma unroll 2
        for (int ix = 0; ix < xn; ++ix) {
            const int x = min(xs + xstep * ix, xlast);
            union { uint4 u; __half2 h[4]; } v;
            v.u = row[(size_t)x * (FC / 8)];
            a0 = __hmax2(a0, v.h[0]);
            a1 = __hmax2(a1, v.h[1]);
            a2 = __hmax2(a2, v.h[2]);
            a3 = __hmax2(a3, v.h[3]);
        }
    }

    const size_t o = ((size_t)roi * (POOL * POOL) + bin) * FC + (size_t)t * 8;
    float2 f0 = __half22float2(a0), f1 = __half22float2(a1);
    float2 f2 = __half22float2(a2), f3 = __half22float2(a3);
    float4* op = reinterpret_cast<float4*>(out + o);
    op[0] = make_float4(f0.x, f0.y, f1.x, f1.y);
    op[1] = make_float4(f2.x, f2.y, f3.x, f3.y);
}

extern "C" void kernel_launch(void* const* d_in, const int* in_sizes, int n_in,
                              void* d_out, int out_size) {
    const float* features = (const float*)d_in[0];  // [1,50,50,1024] fp32
    const float* rois     = (const float*)d_in[1];  // [N,4] fp32
    const int nrois = in_sizes[1] / 4;

    build_kernel<<<CELLS / 4, 512>>>(features);     // 625 blocks

    dim3 grid(13, nrois);   // 13 bin-quads x N rois (52 slots, 49 used)
    roipool_kernel<<<grid, 512>>>(rois, (float*)d_out);
}

// round 16
// speedup vs baseline: 1.4790x; 1.4790x over previous
#include <cuda_runtime.h>
#include <cuda_fp16.h>
#include <math.h>

#define FH 50
#define FW 50
#define FC 1024
#define POOL 7
#define CELLS (FH * FW)
#define MAPW (CELLS * FC / 8)   // uint4 elements per map

// One contiguous pyramid: [0]=F (rn fp16), [1]=R (vert pair max), [2]=M2 (2x2 max).
// rn is monotone and max returns an input, so max(rn(a),rn(b)) == rn(max(a,b)):
// the fp16 pyramid equals rn() of the fp32 pyramid exactly.
__device__ __half g_pyr[3 * CELLS * FC];

__device__ __forceinline__ float4 max4(float4 a, float4 b) {
    return make_float4(fmaxf(a.x, b.x), fmaxf(a.y, b.y),
                       fmaxf(a.z, b.z), fmaxf(a.w, b.w));
}

// Build v3: 256 threads = 2 consecutive cells x 128 lanes (the proven fast
// block shape). Each thread loads its own vertical pair (2 cells), computes R;
// the horizontal neighbor's R comes from smem for group 0, and is computed
// directly by group 1 (block boundary) and at row edges. Avg 3 cells read per
// thread instead of 4. M2 = hmax(R(x), R(x+1)) in fp16 — exact by monotonicity.
__global__ void __launch_bounds__(256) build_kernel(const float* __restrict__ fm) {
    __shared__ uint4 sR[2][128];     // fp16 R per cell-group per lane (4 KB)

    const int g    = threadIdx.x >> 7;
    const int lane = threadIdx.x & 127;
    const int c    = blockIdx.x * 2 + g;      // linear cell 0..2499
    const int y = c / FW;
    const int x = c - y * FW;
    const int yp = min(y + 1, FH - 1);
    const int xp = min(x + 1, FW - 1);

    const float4* f = reinterpret_cast<const float4*>(fm);
    const int l2 = lane * 2;

    float4 a00 = f[c * 256 + l2],              b00 = f[c * 256 + l2 + 1];
    float4 a10 = f[(yp * FW + x) * 256 + l2],  b10 = f[(yp * FW + x) * 256 + l2 + 1];

    float4 ra = max4(a00, a10);
    float4 rb = max4(b00, b10);

    union { __half2 h[4]; uint4 u; } pf, pr;
    pf.h[0] = __floats2half2_rn(a00.x, a00.y); pf.h[1] = __floats2half2_rn(a00.z, a00.w);
    pf.h[2] = __floats2half2_rn(b00.x, b00.y); pf.h[3] = __floats2half2_rn(b00.z, b00.w);
    pr.h[0] = __floats2half2_rn(ra.x, ra.y);   pr.h[1] = __floats2half2_rn(ra.z, ra.w);
    pr.h[2] = __floats2half2_rn(rb.x, rb.y);   pr.h[3] = __floats2half2_rn(rb.z, rb.w);

    uint4* pyr = reinterpret_cast<uint4*>(g_pyr);
    const int i = c * 128 + lane;
    pyr[i]        = pf.u;
    pyr[MAPW + i] = pr.u;
    sR[g][lane]   = pr.u;
    __syncthreads();

    // Neighbor cell's R (same lane).
    union { __half2 h[4]; uint4 u; } nr;
    if (xp == x) {
        nr.u = pr.u;                 // right edge of row: neighbor = self
    } else if (g == 0) {
        nr.u = sR[1][lane];          // in-block neighbor (c+1 == y*FW+xp)
    } else {
        const int cn = y * FW + xp;  // block-boundary: compute directly
        float4 a01 = f[cn * 256 + l2],             b01 = f[cn * 256 + l2 + 1];
        float4 a11 = f[(yp * FW + xp) * 256 + l2], b11 = f[(yp * FW + xp) * 256 + l2 + 1];
        float4 qa = max4(a01, a11);
        float4 qb = max4(b01, b11);
        nr.h[0] = __floats2half2_rn(qa.x, qa.y); nr.h[1] = __floats2half2_rn(qa.z, qa.w);
        nr.h[2] = __floats2half2_rn(qb.x, qb.y); nr.h[3] = __floats2half2_rn(qb.z, qb.w);
    }

    union { __half2 h[4]; uint4 u; } pm;
    pm.h[0] = __hmax2(pr.h[0], nr.h[0]);
    pm.h[1] = __hmax2(pr.h[1], nr.h[1]);
    pm.h[2] = __hmax2(pr.h[2], nr.h[2]);
    pm.h[3] = __hmax2(pr.h[3], nr.h[3]);
    pyr[2 * MAPW + i] = pm.u;
}

// 256-thread blocks, TWO bins per block (R14's measured-best packaging):
// thread group (tid>>7) owns one bin, its 128 threads own one uint4 lane
// (8 halves) each. Inline geometry + pyramid sampling.
__global__ void __launch_bounds__(256) roipool_kernel(
    const float* __restrict__ rois,  // [N,4] (y1,x1,y2,x2) normalized
    float* __restrict__ out)         // [N,7,7,1024] fp32
{
    const int bin = blockIdx.x * 2 + (threadIdx.x >> 7);   // 0..49
    if (bin >= 49) return;           // last block's second group idles
    const int roi = blockIdx.y;
    const int by = bin / POOL;
    const int bx = bin - by * POOL;

    const float4 r = reinterpret_cast<const float4*>(rois)[roi];
    const int h0 = (int)(FH * r.x);
    const int w0 = (int)(FW * r.y);
    const int h1 = (int)(FH * r.z);
    const int w1 = (int)(FW * r.w);
    const int rh = h1 - h0;
    const int rw = w1 - w0;
    const int hstep = rh / POOL;
    const int wstep = rw / POOL;

    int sh = by * hstep;
    int eh = (by < POOL - 1) ? sh + hstep : rh;
    if (sh == eh) { if (eh < rh) eh += 1; else sh -= 1; }
    int sw = bx * wstep;
    int ew = (bx < POOL - 1) ? sw + wstep : rw;
    if (sw == ew) { if (ew < rw) ew += 1; else sw -= 1; }

    const int ys = max(h0 + sh, 0);
    const int ye = h0 + eh;          // <= FH
    const int xs = max(w0 + sw, 0);
    const int xe = w0 + ew;          // <= FW
    const int h = ye - ys;
    const int w = xe - xs;

    // Select map + sampling grid (overlapping clamped samples; max idempotent).
    const uint4* base;
    int yn, xn, xstep, ylast, xlast;
    if (h >= 2) {
        yn = (h + 1) >> 1; ylast = ye - 2;
        if (w >= 2) { base = reinterpret_cast<const uint4*>(g_pyr) + 2 * MAPW;
                      xn = (w + 1) >> 1; xstep = 2; xlast = xe - 2; }
        else        { base = reinterpret_cast<const uint4*>(g_pyr) + MAPW;
                      xn = 1; xstep = 2; xlast = xs; }
    } else {        // h == 1: single row from F
        base = reinterpret_cast<const uint4*>(g_pyr);
        yn = 1; ylast = ys; xn = w; xstep = 1; xlast = xe - 1;
    }

    const int t = threadIdx.x & 127; // uint4 lane (8 halves)
    const __half2 ninf = __float2half2_rn(-INFINITY);
    __half2 a0 = ninf, a1 = ninf, a2 = ninf, a3 = ninf;

    for (int iy = 0; iy < yn; ++iy) {
        const int y = min(ys + 2 * iy, ylast);
        const uint4* row = base + (size_t)(y * FW) * (FC / 8) + t;
        #pragma unroll 2
        for (int ix = 0; ix < xn; ++ix) {
            const int x = min(xs + xstep * ix, xlast);
            union { uint4 u; __half2 h[4]; } v;
            v.u = row[(size_t)x * (FC / 8)];
            a0 = __hmax2(a0, v.h[0]);
            a1 = __hmax2(a1, v.h[1]);
            a2 = __hmax2(a2, v.h[2]);
            a3 = __hmax2(a3, v.h[3]);
        }
    }

    const size_t o = ((size_t)roi * (POOL * POOL) + bin) * FC + (size_t)t * 8;
    float2 f0 = __half22float2(a0), f1 = __half22float2(a1);
    float2 f2 = __half22float2(a2), f3 = __half22float2(a3);
    float4* op = reinterpret_cast<float4*>(out + o);
    op[0] = make_float4(f0.x, f0.y, f1.x, f1.y);
    op[1] = make_float4(f2.x, f2.y, f3.x, f3.y);
}

extern "C" void kernel_launch(void* const* d_in, const int* in_sizes, int n_in,
                              void* d_out, int out_size) {
    const float* features = (const float*)d_in[0];  // [1,50,50,1024] fp32
    const float* rois     = (const float*)d_in[1];  // [N,4] fp32
    const int nrois = in_sizes[1] / 4;

    build_kernel<<<CELLS / 2, 256>>>(features);     // 1250 blocks

    dim3 grid(25, nrois);   // 25 bin-pairs x N rois
    roipool_kernel<<<grid, 256>>>(rois, (float*)d_out);
}